// round 16
// baseline (speedup 1.0000x reference)
#include <cuda_runtime.h>

#define HW    512
#define NIMG  16
#define TILE  64
#define TPB   256           // slowB
#define TPBA  512           // phaseA / finalize
#define EPSF  1e-8f

// Phase A: iterations 0..3 (KA=4). Vertical halo RAY=7 (78 rows); horizontal
// halo RAX=8 (80 cols, keeps global float4 loads 16B-aligned).
// cl exact at halo 2; lab_4 exact at halo 3; drain scan lies entirely inside
// the exactly-computed region (no free-run garbage in the scan).
#define RAY   7
#define RAX   8
#define WRR   78            // rows
#define WS    80            // col count & stride; 320B rows, 16B aligned
#define KA    4
#define CLW   68            // cl band (halo 2); also pool row stride
#define DW    66
#define NRING 528           // 68*68 - 64*64

// slowB: iterations 4..20 (17 iters), lab_4 needed at halo 20
#define RB 20
#define WB 104
#define KB 17

__device__ float g_lab[2][NIMG][HW][HW];   // lab_4 (written only where nonzero)
__device__ float g_cl [2][NIMG][HW][HW];   // cl after 4 iters (always written)
__device__ int   g_flag[2][NIMG][64];      // per-tile: lab_4 tile has nonzeros
__device__ float g_part[2][NIMG][64][2];   // per-tile partial sums

__device__ __forceinline__ int iclamp(int v) {
    return v < 0 ? 0 : (v > HW - 1 ? HW - 1 : v);
}

__device__ __forceinline__ void ring_cell(int k, int& i, int& j) {
    if (k < 272) {
        int kk = k;
        if (kk < 136) { i = -2 + kk / 68; }
        else          { kk -= 136; i = 64 + kk / 68; }
        j = -2 + kk % 68;
    } else {
        const int k3 = k - 272;
        i = k3 >> 2;
        const int j4 = k3 & 3;
        j = (j4 < 2) ? (j4 - 2) : (62 + j4);
    }
}

// ---------------------------------------------------------------------------
__global__ void __launch_bounds__(TPBA, 4) phaseA_kernel(const float* __restrict__ x,
                                                         const int*   __restrict__ y) {
    extern __shared__ float sm[];
    float* bufA = sm;                    // WRR x WS
    float* bufB = sm + WRR * WS;         // WRR x WS
    float* ring = sm + 2 * WRR * WS;     // NRING (+pad)
    __shared__ float s_r0[16], s_r1[16];

    const int tid = threadIdx.x;
    const int tx = tid & 31, ty = tid >> 5;   // ty 0..15
    const int tileIdx = blockIdx.x;
    const int img  = blockIdx.y;
    const int pipe = blockIdx.z;          // 0 = pred (x), 1 = label (one-hot y)
    const int tY = (tileIdx >> 3) * TILE;
    const int tX = (tileIdx & 7)  * TILE;
    const int gy0 = tY - RAY, gx0 = tX - RAX;
    const bool edge = (tY == 0) || (tX == 0) || (tY == HW - TILE) || (tX == HW - TILE);
    const int vTop = (tY == 0)         ? 1 : 0;
    const int vBot = (tY == HW - TILE) ? 1 : 0;
    const int vL   = (tX == 0)         ? 1 : 0;
    const int vR   = (tX == HW - TILE) ? 1 : 0;

    const float* __restrict__ xin = x + (size_t)img * HW * HW;
    const int*   __restrict__ yin = y + (size_t)(img >> 1) * HW * HW;
    const int cls = img & 1;

    // Vectorized halo load for ALL tiles: rows clamped (always in-bounds),
    // vL/vR column strips replicated afterwards from loaded cols.
    if (!vL && !vR) {
        if (pipe == 0) {
            for (int u = tid; u < WRR * 20; u += TPBA) {
                const int i = u / 20, cu = u - i * 20;
                *(float4*)(bufA + i * WS + cu * 4) =
                    *(const float4*)(xin + iclamp(gy0 + i) * HW + gx0 + cu * 4);
            }
        } else {
            for (int u = tid; u < WRR * 20; u += TPBA) {
                const int i = u / 20, cu = u - i * 20;
                const int4 s = *(const int4*)(yin + iclamp(gy0 + i) * HW + gx0 + cu * 4);
                *(float4*)(bufA + i * WS + cu * 4) =
                    make_float4((s.x == cls) ? 1.0f : 0.0f, (s.y == cls) ? 1.0f : 0.0f,
                                (s.z == cls) ? 1.0f : 0.0f, (s.w == cls) ? 1.0f : 0.0f);
            }
        }
    } else {
        const int uLo = vL ? 2 : 0;   // 18 valid units
        if (pipe == 0) {
            for (int u = tid; u < WRR * 18; u += TPBA) {
                const int i = u / 18, cu = uLo + (u - i * 18);
                *(float4*)(bufA + i * WS + cu * 4) =
                    *(const float4*)(xin + iclamp(gy0 + i) * HW + gx0 + cu * 4);
            }
        } else {
            for (int u = tid; u < WRR * 18; u += TPBA) {
                const int i = u / 18, cu = uLo + (u - i * 18);
                const int4 s = *(const int4*)(yin + iclamp(gy0 + i) * HW + gx0 + cu * 4);
                *(float4*)(bufA + i * WS + cu * 4) =
                    make_float4((s.x == cls) ? 1.0f : 0.0f, (s.y == cls) ? 1.0f : 0.0f,
                                (s.z == cls) ? 1.0f : 0.0f, (s.w == cls) ? 1.0f : 0.0f);
            }
        }
    }

    // Ring offsets hoisted (fixed per thread across iterations).
    int roff0, ci0, roff1 = -1, ci1 = 0;
    {
        int i, j;
        ring_cell(tid, i, j);
        roff0 = (RAY + i) * WS + (RAX + j);
        ci0   = (i + 2) * CLW + (j + 2);
        if (tid < NRING - TPBA) {
            ring_cell(tid + TPBA, i, j);
            roff1 = (RAY + i) * WS + (RAX + j);
            ci1   = (i + 2) * CLW + (j + 2);
        }
    }
    ring[tid] = 0.0f;
    if (tid < NRING - TPBA) ring[tid + TPBA] = 0.0f;

    __syncthreads();
    if (vL) for (int i = tid; i < WRR; i += TPBA) {
        const float v = bufA[i * WS + 8];
        #pragma unroll
        for (int j = 0; j < 8; j++) bufA[i * WS + j] = v;
    }
    if (vR) for (int i = tid; i < WRR; i += TPBA) {
        const float v = bufA[i * WS + RAX + TILE - 1];
        #pragma unroll
        for (int j = 0; j < 8; j++) bufA[i * WS + RAX + TILE + j] = v;
    }
    __syncthreads();

    // cl in registers: warp ty owns rows ty*4..ty*4+3; thread cols tx, tx+32.
    float clr[2][4];
    #pragma unroll
    for (int c = 0; c < 2; c++)
        #pragma unroll
        for (int r = 0; r < 4; r++) clr[c][r] = 0.0f;

    float* pin  = bufA;
    float* pout = bufB;
    bool drained = false;

    for (int it = 0; it < KA; it++) {
        const int Hh = 6 - it;                          // output halo: 6,5,4,3
        const int r0 = RAY - Hh, r1 = RAY + TILE + Hh;  // row band
        const int cLo = RAX - Hh, cHi = RAX + TILE + Hh;// col validity window
        const int qlo = (cLo + 3) >> 2, qhi = (cHi - 4) >> 2;
        const int units = (r1 - r0) * 20;
        int nz = 0;
        for (int u = tid; u < units; u += TPBA) {
            const int rr = u / 20;
            const int c4 = u - rr * 20;
            const int base = (r0 + rr) * WS + c4 * 4;
            const float4 c = *(const float4*)(pin + base);
            if ((c.x == 0.0f) & (c.y == 0.0f) & (c.z == 0.0f) & (c.w == 0.0f)) {
                *(float4*)(pout + base) = make_float4(0.0f, 0.0f, 0.0f, 0.0f);
            } else {
                const float4 up = *(const float4*)(pin + base - WS);
                const float4 dn = *(const float4*)(pin + base + WS);
                const float lft = pin[base - 1];
                const float rgt = pin[base + 4];
                float4 o;
                o.x = fminf(fminf(fminf(lft, c.y), c.x), fminf(up.x, dn.x));
                o.y = fminf(fminf(fminf(c.x, c.z), c.y), fminf(up.y, dn.y));
                o.z = fminf(fminf(fminf(c.y, c.w), c.z), fminf(up.z, dn.z));
                o.w = fminf(fminf(fminf(c.z, rgt), c.w), fminf(up.w, dn.w));
                *(float4*)(pout + base) = o;
                if (c4 >= qlo && c4 <= qhi) {
                    nz |= (o.x != 0.0f) | (o.y != 0.0f) | (o.z != 0.0f) | (o.w != 0.0f);
                } else {
                    const int j0 = c4 * 4;
                    nz |= ((o.x != 0.0f) & (j0     >= cLo) & (j0     < cHi));
                    nz |= ((o.y != 0.0f) & (j0 + 1 >= cLo) & (j0 + 1 < cHi));
                    nz |= ((o.z != 0.0f) & (j0 + 2 >= cLo) & (j0 + 2 < cHi));
                    nz |= ((o.w != 0.0f) & (j0 + 3 >= cLo) & (j0 + 3 < cHi));
                }
            }
        }
        const int any = __syncthreads_or(nz);

        // Re-clamp virtual band of pout (edge tiles) => exact replicate pad.
        if (edge) {
            if (vTop) for (int i = r0 + ty; i < RAY; i += 16) {
                float* d = pout + i * WS; const float* s = pout + RAY * WS;
                for (int j = cLo + tx; j < cHi; j += 32) d[j] = s[j];
            }
            if (vBot) for (int i = RAY + TILE + ty; i < r1; i += 16) {
                float* d = pout + i * WS; const float* s = pout + (RAY + TILE - 1) * WS;
                for (int j = cLo + tx; j < cHi; j += 32) d[j] = s[j];
            }
            __syncthreads();
            if (vL) for (int i = r0 + ty; i < r1; i += 16) {
                const float s = pout[i * WS + RAX];
                for (int j = cLo + tx; j < RAX; j += 32) pout[i * WS + j] = s;
            }
            if (vR) for (int i = r0 + ty; i < r1; i += 16) {
                const float s = pout[i * WS + RAX + TILE - 1];
                for (int j = RAX + TILE + tx; j < cHi; j += 32) pout[i * WS + j] = s;
            }
            __syncthreads();
        }

        // Tile cl update (registers), ballot-skipped; when band is fully zero
        // (any==0) maxpool3(nl) == 0 on the cl band => t = lab directly.
        {
            const int rbase = RAY + ty * 4;
            float labv[2][4];
            int lz = 0;
            #pragma unroll
            for (int c = 0; c < 2; c++) {
                const float* lp = pin + rbase * WS + RAX + tx + c * 32;
                #pragma unroll
                for (int r = 0; r < 4; r++) {
                    labv[c][r] = lp[r * WS];
                    lz |= (labv[c][r] != 0.0f);
                }
            }
            if (__ballot_sync(0xffffffffu, lz)) {
                if (any) {
                    #pragma unroll
                    for (int c = 0; c < 2; c++) {
                        const int jj = RAX + tx + c * 32;
                        const float* p = pout + (rbase - 1) * WS + jj;
                        float h0 = fmaxf(fmaxf(p[-1], p[0]), p[1]); p += WS;
                        float h1 = fmaxf(fmaxf(p[-1], p[0]), p[1]); p += WS;
                        #pragma unroll
                        for (int r = 0; r < 4; r++) {
                            const float h2 = fmaxf(fmaxf(p[-1], p[0]), p[1]); p += WS;
                            const float m = fmaxf(fmaxf(h0, h1), h2);
                            const float t = labv[c][r] - m;
                            if (t > 0.0f) {
                                const float cv = clr[c][r];
                                clr[c][r] = cv + fmaxf((1.0f - cv) * t, 0.0f);
                            }
                            h0 = h1; h1 = h2;
                        }
                    }
                } else {
                    #pragma unroll
                    for (int c = 0; c < 2; c++)
                        #pragma unroll
                        for (int r = 0; r < 4; r++) {
                            const float t = labv[c][r];
                            if (t > 0.0f) {
                                const float cv = clr[c][r];
                                clr[c][r] = cv + fmaxf((1.0f - cv) * t, 0.0f);
                            }
                        }
                }
            }
        }

        // Ring cl update (halo-2 border cells), per-cell lab gate.
        {
            const float lab = pin[roff0];
            if (lab != 0.0f) {
                float m = 0.0f;
                if (any) {
                    const float* p = pout + roff0;
                    m =          fmaxf(fmaxf(p[-1 - WS], p[-WS]), p[1 - WS]);
                    m = fmaxf(m, fmaxf(fmaxf(p[-1],      p[0]),  p[1]));
                    m = fmaxf(m, fmaxf(fmaxf(p[-1 + WS], p[WS]), p[1 + WS]));
                }
                const float t = lab - m;
                if (t > 0.0f) {
                    const float cv = ring[tid];
                    ring[tid] = cv + fmaxf((1.0f - cv) * t, 0.0f);
                }
            }
            if (roff1 >= 0) {
                const float lab2 = pin[roff1];
                if (lab2 != 0.0f) {
                    float m = 0.0f;
                    if (any) {
                        const float* p = pout + roff1;
                        m =          fmaxf(fmaxf(p[-1 - WS], p[-WS]), p[1 - WS]);
                        m = fmaxf(m, fmaxf(fmaxf(p[-1],      p[0]),  p[1]));
                        m = fmaxf(m, fmaxf(fmaxf(p[-1 + WS], p[WS]), p[1 + WS]));
                    }
                    const float t = lab2 - m;
                    if (t > 0.0f) {
                        const float cv = ring[tid + TPBA];
                        ring[tid + TPBA] = cv + fmaxf((1.0f - cv) * t, 0.0f);
                    }
                }
            }
        }
        __syncthreads();
        float* tmp = pin; pin = pout; pout = tmp;
        if (!any) { drained = true; break; }
    }

    int tnz = 0;
    if (!drained) {
        // Nonzero scan of lab_4: rows [RAY-2, RAY+66) = [5,73) (exact halo-2
        // rows), cols aligned window [4,76). Both lie inside lab_4's
        // exactly-computed region (exact cols [4,76), rows [4,74)).
        int hz = 0;
        for (int u = tid; u < 68 * 18; u += TPBA) {
            const int r = u / 18, cu = u - r * 18;
            const float4 c = *(const float4*)(pin + (5 + r) * WS + 4 + cu * 4);
            const int nzv = (c.x != 0.0f) | (c.y != 0.0f) | (c.z != 0.0f) | (c.w != 0.0f);
            hz |= nzv;
            tnz |= nzv & (r >= 2) & (r < 66);
        }
        hz  = __syncthreads_or(hz);
        tnz = __syncthreads_or(tnz);
        drained = !hz;
    }

    // Publish cl (registers) always; lab_4 only if tile may be nonzero; flag.
    float* __restrict__ gc = &g_cl[pipe][img][0][0];
    #pragma unroll
    for (int r = 0; r < 4; r++) {
        const int row = ty * 4 + r;
        float* go = gc + (tY + row) * HW + tX;
        go[tx]      = clr[0][r];
        go[tx + 32] = clr[1][r];
    }
    if (tnz) {
        float* __restrict__ gl = &g_lab[pipe][img][0][0];
        #pragma unroll
        for (int r = 0; r < 4; r++) {
            const int row = ty * 4 + r;
            const float* lr = pin + (RAY + row) * WS + RAX;
            float* go = gl + (tY + row) * HW + tX;
            go[tx]      = lr[tx];
            go[tx + 32] = lr[tx + 32];
        }
    }
    if (tid == 0) g_flag[pipe][img][tileIdx] = tnz;

    if (!drained) return;   // slowB owns the partials for this tile

    // ---------- drained: stage cl into 68x68 (stride CLW), pools, reduce ----
    float* CLS = pout;
    #pragma unroll
    for (int r = 0; r < 4; r++) {
        const int row = ty * 4 + r;
        float* cr = CLS + (2 + row) * CLW + 2;
        cr[tx]      = clr[0][r];
        cr[tx + 32] = clr[1][r];
    }
    CLS[ci0] = ring[tid];
    if (roff1 >= 0) CLS[ci1] = ring[tid + TPBA];
    __syncthreads();

    if (edge) {
        if (vTop)
            for (int k = tid; k < 2 * CLW; k += TPBA) CLS[(k / CLW) * CLW + k % CLW] = CLS[2 * CLW + k % CLW];
        if (vBot)
            for (int k = tid; k < 2 * CLW; k += TPBA) CLS[(66 + k / CLW) * CLW + k % CLW] = CLS[65 * CLW + k % CLW];
        __syncthreads();
        if (vL)
            for (int k = tid; k < 2 * CLW; k += TPBA) CLS[(k >> 1) * CLW + (k & 1)] = CLS[(k >> 1) * CLW + 2];
        if (vR)
            for (int k = tid; k < 2 * CLW; k += TPBA) CLS[(k >> 1) * CLW + 66 + (k & 1)] = CLS[(k >> 1) * CLW + 65];
        __syncthreads();
    }

    // HB = hmax3 rows (stride CLW, valid cols 0..65), vectorized.
    float* HB = pin;
    for (int u = tid; u < 68 * 17; u += TPBA) {
        const int r = u / 17, cu = u - r * 17;
        const int b = r * CLW + cu * 4;
        const float4 A = *(const float4*)(CLS + b);
        const float4 B = *(const float4*)(CLS + b + 4);
        float4 o;
        o.x = fmaxf(fmaxf(A.x, A.y), A.z);
        o.y = fmaxf(fmaxf(A.y, A.z), A.w);
        o.z = fmaxf(fmaxf(A.z, A.w), B.x);
        o.w = fmaxf(fmaxf(A.w, B.x), B.y);
        *(float4*)(HB + b) = o;
    }
    __syncthreads();
    float* D = CLS;
    for (int u = tid; u < 66 * 17; u += TPBA) {
        const int d = u / 17, cu = u - d * 17;
        const int b = d * CLW + cu * 4;
        const float4 A  = *(const float4*)(HB + b);
        const float4 Bv = *(const float4*)(HB + b + CLW);
        const float4 Cv = *(const float4*)(HB + b + 2 * CLW);
        float4 o;
        o.x = fmaxf(fmaxf(A.x, Bv.x), Cv.x);
        o.y = fmaxf(fmaxf(A.y, Bv.y), Cv.y);
        o.z = fmaxf(fmaxf(A.z, Bv.z), Cv.z);
        o.w = fmaxf(fmaxf(A.w, Bv.w), Cv.w);
        *(float4*)(D + b) = o;
    }
    __syncthreads();
    if (edge) {
        if (vTop) for (int e = tid; e < DW; e += TPBA) D[e]              = D[CLW + e];
        if (vBot) for (int e = tid; e < DW; e += TPBA) D[65 * CLW + e]   = D[64 * CLW + e];
        __syncthreads();
        if (vL)   for (int d = tid; d < DW; d += TPBA) D[d * CLW]        = D[d * CLW + 1];
        if (vR)   for (int d = tid; d < DW; d += TPBA) D[d * CLW + 65]   = D[d * CLW + 64];
        __syncthreads();
    }

    // Final plus-min + fused reduction, vectorized (4 cells per unit).
    float s0 = 0.0f, s1 = 0.0f;
    for (int u = tid; u < 1024; u += TPBA) {
        const int i2 = u >> 4, cu = u & 15;
        const int c0 = cu * 4;
        const float* rc = D + (i2 + 1) * CLW + c0;
        const float4 A = *(const float4*)(rc);
        const float b0 = rc[4], b1 = rc[5];
        float v0 = fminf(A.y, fminf(A.x, A.z));
        float v1 = fminf(A.z, fminf(A.y, A.w));
        float v2 = fminf(A.w, fminf(A.z, b0));
        float v3 = fminf(b0,  fminf(A.w, b1));
        {
            const float4 Au = *(const float4*)(rc - CLW);
            v0 = fminf(v0, Au.y); v1 = fminf(v1, Au.z); v2 = fminf(v2, Au.w);
            v3 = fminf(v3, rc[-CLW + 4]);
        }
        {
            const float4 Ad = *(const float4*)(rc + CLW);
            v0 = fminf(v0, Ad.y); v1 = fminf(v1, Ad.z); v2 = fminf(v2, Ad.w);
            v3 = fminf(v3, rc[CLW + 4]);
        }
        const int gy = tY + i2, gxb = tX + c0;
        float w0, w1, w2, w3;
        if (pipe == 0) {
            const int4 yy = *(const int4*)(yin + gy * HW + gxb);
            w0 = (yy.x == cls) ? 1.0f : 0.0f;
            w1 = (yy.y == cls) ? 1.0f : 0.0f;
            w2 = (yy.z == cls) ? 1.0f : 0.0f;
            w3 = (yy.w == cls) ? 1.0f : 0.0f;
        } else {
            const float4 xx = *(const float4*)(xin + gy * HW + gxb);
            w0 = xx.x; w1 = xx.y; w2 = xx.z; w3 = xx.w;
        }
        s0 += v0 * w0 + v1 * w1 + v2 * w2 + v3 * w3;
        s1 += (v0 + v1) + (v2 + v3);
    }
    for (int o = 16; o > 0; o >>= 1) {
        s0 += __shfl_down_sync(0xffffffffu, s0, o);
        s1 += __shfl_down_sync(0xffffffffu, s1, o);
    }
    if (tx == 0) { s_r0[ty] = s0; s_r1[ty] = s1; }
    __syncthreads();
    if (tid < 16) {
        s0 = s_r0[tid]; s1 = s_r1[tid];
        for (int o = 8; o > 0; o >>= 1) {
            s0 += __shfl_down_sync(0xffffu, s0, o);
            s1 += __shfl_down_sync(0xffffu, s1, o);
        }
        if (tid == 0) {
            g_part[pipe][img][tileIdx][0] = s0;
            g_part[pipe][img][tileIdx][1] = s1;
        }
    }
}

// ---------------------------------------------------------------------------
// slowB: tiles with any 3x3 covering flag set: iterations 4..20 + pools +
// reduction. Exits immediately otherwise.
// ---------------------------------------------------------------------------
__global__ void __launch_bounds__(TPB) slowB_kernel(const float* __restrict__ x,
                                                    const int*   __restrict__ y) {
    extern __shared__ float sm[];
    float* bufA = sm;
    float* bufB = sm + WB * WB;
    float* CLB  = sm + 2 * WB * WB;
    __shared__ float s_r0[8], s_r1[8];
    __shared__ int s_flags[9];

    const int tid = threadIdx.x;
    const int tx = tid & 31, ty = tid >> 5;
    const int tileIdx = blockIdx.x;
    const int img  = blockIdx.y;
    const int pipe = blockIdx.z;
    const int tr = tileIdx >> 3, tc = tileIdx & 7;
    const int tY = tr * TILE, tX = tc * TILE;
    const int gy0 = tY - RB, gx0 = tX - RB;
    const bool edge = (tY == 0) || (tX == 0) || (tY == HW - TILE) || (tX == HW - TILE);

    if (tid < 9) {
        const int rr = tr + tid / 3 - 1, cc = tc + tid % 3 - 1;
        int f = 0;
        if (rr >= 0 && rr < 8 && cc >= 0 && cc < 8) f = g_flag[pipe][img][rr * 8 + cc];
        s_flags[tid] = f;
    }
    __syncthreads();
    int anyLab = 0;
    #pragma unroll
    for (int k = 0; k < 9; k++) anyLab |= s_flags[k];
    if (!anyLab) return;

    const float* __restrict__ gl = &g_lab[pipe][img][0][0];
    const float* __restrict__ gc = &g_cl [pipe][img][0][0];

    for (int i = ty; i < CLW; i += 8) {
        const int gy = iclamp(tY - 2 + i);
        float* d = CLB + i * CLW;
        for (int j = tx; j < CLW; j += 32) d[j] = gc[gy * HW + iclamp(tX - 2 + j)];
    }
    for (int i = ty; i < WB; i += 8) {
        const int gy = iclamp(gy0 + i);
        const int fr = (gy >> 6) - (tr - 1);
        for (int j = tx; j < WB; j += 32) {
            const int gx = iclamp(gx0 + j);
            const int fc = (gx >> 6) - (tc - 1);
            bufA[i * WB + j] = s_flags[fr * 3 + fc] ? gl[gy * HW + gx] : 0.0f;
        }
    }
    __syncthreads();

    float* pin  = bufA;
    float* pout = bufB;
    for (int it = 0; it < KB; it++) {
        int Hh = 19 - it; if (Hh < 3) Hh = 3;
        const int r0 = RB - Hh, r1 = RB + TILE + Hh;
        int nz = 0;
        for (int i = r0 + ty; i < r1; i += 8) {
            const int gy = gy0 + i;
            if (gy < 0 || gy >= HW) continue;
            const int iu = (gy > 0)      ? i - 1 : i;
            const int id = (gy < HW - 1) ? i + 1 : i;
            for (int j = r0 + tx; j < r1; j += 32) {
                const int gx = gx0 + j;
                if (gx < 0 || gx >= HW) continue;
                const int jl = (gx > 0)      ? j - 1 : j;
                const int jr = (gx < HW - 1) ? j + 1 : j;
                float v = pin[i * WB + j];
                v = fminf(v, pin[iu * WB + j]);
                v = fminf(v, pin[id * WB + j]);
                v = fminf(v, pin[i * WB + jl]);
                v = fminf(v, pin[i * WB + jr]);
                pout[i * WB + j] = v;
                nz |= (v != 0.0f);
            }
        }
        const int any = __syncthreads_or(nz);
        for (int i = RB - 2 + ty; i < RB + TILE + 2; i += 8) {
            const int gy = gy0 + i;
            if (gy < 0 || gy >= HW) continue;
            const int iu = (gy > 0)      ? i - 1 : i;
            const int id = (gy < HW - 1) ? i + 1 : i;
            for (int j = RB - 2 + tx; j < RB + TILE + 2; j += 32) {
                const int gx = gx0 + j;
                if (gx < 0 || gx >= HW) continue;
                const int jl = (gx > 0)      ? j - 1 : j;
                const int jr = (gx < HW - 1) ? j + 1 : j;
                float m;
                m =          pout[iu * WB + jl];
                m = fmaxf(m, pout[iu * WB + j ]);
                m = fmaxf(m, pout[iu * WB + jr]);
                m = fmaxf(m, pout[i  * WB + jl]);
                m = fmaxf(m, pout[i  * WB + j ]);
                m = fmaxf(m, pout[i  * WB + jr]);
                m = fmaxf(m, pout[id * WB + jl]);
                m = fmaxf(m, pout[id * WB + j ]);
                m = fmaxf(m, pout[id * WB + jr]);
                const float lab = pin[i * WB + j];
                const int ci = (i - (RB - 2)) * CLW + (j - (RB - 2));
                const float cl = CLB[ci];
                const float t = fmaxf(lab - m, 0.0f);
                CLB[ci] = cl + fmaxf((1.0f - cl) * t, 0.0f);
            }
        }
        __syncthreads();
        float* tmp = pin; pin = pout; pout = tmp;
        if (!any) break;
    }

    if (edge) {
        if (tY == 0)
            for (int k = tid; k < 2 * CLW; k += TPB) CLB[(k / CLW) * CLW + k % CLW] = CLB[2 * CLW + k % CLW];
        if (tY == HW - TILE)
            for (int k = tid; k < 2 * CLW; k += TPB) CLB[(66 + k / CLW) * CLW + k % CLW] = CLB[65 * CLW + k % CLW];
        __syncthreads();
        if (tX == 0)
            for (int k = tid; k < 2 * CLW; k += TPB) CLB[(k >> 1) * CLW + (k & 1)] = CLB[(k >> 1) * CLW + 2];
        if (tX == HW - TILE)
            for (int k = tid; k < 2 * CLW; k += TPB) CLB[(k >> 1) * CLW + 66 + (k & 1)] = CLB[(k >> 1) * CLW + 65];
        __syncthreads();
    }

    float* Hb = bufB;
    for (int c = ty; c < CLW; c += 8) {
        const float* r = CLB + c * CLW;
        float* hb = Hb + c * DW;
        for (int e = tx; e < DW; e += 32)
            hb[e] = fmaxf(fmaxf(r[e], r[e + 1]), r[e + 2]);
    }
    __syncthreads();
    float* D = bufA;
    for (int d = ty; d < DW; d += 8) {
        const float* h = Hb + d * DW;
        float* dd = D + d * DW;
        for (int e = tx; e < DW; e += 32)
            dd[e] = fmaxf(fmaxf(h[e], h[e + DW]), h[e + 2 * DW]);
    }
    __syncthreads();
    if (edge) {
        if (tY == 0)          for (int e = tid; e < DW; e += TPB) D[e]           = D[DW + e];
        if (tY == HW - TILE)  for (int e = tid; e < DW; e += TPB) D[65 * DW + e] = D[64 * DW + e];
        __syncthreads();
        if (tX == 0)          for (int d = tid; d < DW; d += TPB) D[d * DW]      = D[d * DW + 1];
        if (tX == HW - TILE)  for (int d = tid; d < DW; d += TPB) D[d * DW + 65] = D[d * DW + 64];
        __syncthreads();
    }

    const float* __restrict__ xin = x + (size_t)img * HW * HW;
    const int*   __restrict__ yin = y + (size_t)(img >> 1) * HW * HW;
    const int cls = img & 1;
    float s0 = 0.0f, s1 = 0.0f;
    for (int i2 = ty; i2 < TILE; i2 += 8) {
        const int gy = tY + i2;
        const float* dc = D + (i2 + 1) * DW;
        for (int j2 = tx; j2 < TILE; j2 += 32) {
            const int e = j2 + 1;
            float v = fminf(fminf(dc[e - 1], dc[e]), dc[e + 1]);
            v = fminf(v, fminf(dc[e - DW], dc[e + DW]));
            const float w = (pipe == 0) ? ((yin[gy * HW + tX + j2] == cls) ? 1.0f : 0.0f)
                                        : xin[gy * HW + tX + j2];
            s0 += v * w;
            s1 += v;
        }
    }
    for (int o = 16; o > 0; o >>= 1) {
        s0 += __shfl_down_sync(0xffffffffu, s0, o);
        s1 += __shfl_down_sync(0xffffffffu, s1, o);
    }
    if (tx == 0) { s_r0[ty] = s0; s_r1[ty] = s1; }
    __syncthreads();
    if (tid < 8) {
        s0 = s_r0[tid]; s1 = s_r1[tid];
        for (int o = 4; o > 0; o >>= 1) {
            s0 += __shfl_down_sync(0xffu, s0, o);
            s1 += __shfl_down_sync(0xffu, s1, o);
        }
        if (tid == 0) {
            g_part[pipe][img][tileIdx][0] = s0;
            g_part[pipe][img][tileIdx][1] = s1;
        }
    }
}

// ---------------------------------------------------------------------------
__global__ void __launch_bounds__(TPBA) finalize_kernel(float* __restrict__ out) {
    __shared__ float sdc[16];
    const int w = threadIdx.x >> 5;
    const int l = threadIdx.x & 31;
    float np = 0.0f, dp = 0.0f, nl2 = 0.0f, dl = 0.0f;
    #pragma unroll
    for (int k = l; k < 64; k += 32) {
        np  += g_part[0][w][k][0];
        dp  += g_part[0][w][k][1];
        nl2 += g_part[1][w][k][0];
        dl  += g_part[1][w][k][1];
    }
    for (int o = 16; o > 0; o >>= 1) {
        np  += __shfl_down_sync(0xffffffffu, np,  o);
        dp  += __shfl_down_sync(0xffffffffu, dp,  o);
        nl2 += __shfl_down_sync(0xffffffffu, nl2, o);
        dl  += __shfl_down_sync(0xffffffffu, dl,  o);
    }
    if (l == 0) {
        const float a = (np  + EPSF) / (dp + EPSF);
        const float b = (nl2 + EPSF) / (dl + EPSF);
        sdc[w] = 2.0f * a * b / (a + b);
    }
    __syncthreads();
    if (threadIdx.x < 32) {
        float dc = (threadIdx.x < 16) ? sdc[threadIdx.x] : 0.0f;
        for (int o = 16; o > 0; o >>= 1) dc += __shfl_down_sync(0xffffffffu, dc, o);
        if (threadIdx.x == 0) out[0] = -(dc * (1.0f / 16.0f));
    }
}

// ---------------------------------------------------------------------------
extern "C" void kernel_launch(void* const* d_in, const int* in_sizes, int n_in,
                              void* d_out, int out_size) {
    const float* x = (const float*)d_in[0];
    const int*   y = (const int*)d_in[1];
    float* out = (float*)d_out;

    const int smA = (2 * WRR * WS + NRING + 16) * (int)sizeof(float);   // 52,096 B
    const int smB = (2 * WB * WB + CLW * CLW) * (int)sizeof(float);     // 105,024 B
    cudaFuncSetAttribute(phaseA_kernel, cudaFuncAttributeMaxDynamicSharedMemorySize, smA);
    cudaFuncSetAttribute(slowB_kernel,  cudaFuncAttributeMaxDynamicSharedMemorySize, smB);

    dim3 grid(64, NIMG, 2);
    phaseA_kernel<<<grid, TPBA, smA>>>(x, y);
    slowB_kernel<<<grid, TPB, smB>>>(x, y);
    finalize_kernel<<<1, TPBA>>>(out);
    (void)in_sizes; (void)n_in; (void)out_size;
}

// round 17
// speedup vs baseline: 1.1801x; 1.1801x over previous
#include <cuda_runtime.h>

#define HW    512
#define NIMG  16
#define TILE  64
#define TPB   256           // slowB
#define TPBA  512           // phaseA / phaseL / finalize
#define EPSF  1e-8f

// Phase A (pred, float): iterations 0..3 (KA=4). RAY=7 (78 rows), RAX=8.
#define RAY   7
#define RAX   8
#define WRR   78
#define WS    80
#define KA    4
#define CLW   68
#define DW    66
#define NRING 528

// slowB: iterations 4..20 (17 iters), lab_4 needed at halo 20
#define RB 20
#define WB 104
#define KB 17

__device__ float g_lab[2][NIMG][HW][HW];
__device__ float g_cl [2][NIMG][HW][HW];
__device__ int   g_flag[2][NIMG][64];
__device__ float g_part[2][NIMG][64][2];

__device__ __forceinline__ int iclamp(int v) {
    return v < 0 ? 0 : (v > HW - 1 ? HW - 1 : v);
}

__device__ __forceinline__ void ring_cell(int k, int& i, int& j) {
    if (k < 272) {
        int kk = k;
        if (kk < 136) { i = -2 + kk / 68; }
        else          { kk -= 136; i = 64 + kk / 68; }
        j = -2 + kk % 68;
    } else {
        const int k3 = k - 272;
        i = k3 >> 2;
        const int j4 = k3 & 3;
        j = (j4 < 2) ? (j4 - 2) : (62 + j4);
    }
}

// ---------------------------------------------------------------------------
// phaseA: pred pipe (pipe 0), float path — unchanged from R16, launched z=1.
// ---------------------------------------------------------------------------
__global__ void __launch_bounds__(TPBA, 4) phaseA_kernel(const float* __restrict__ x,
                                                         const int*   __restrict__ y) {
    extern __shared__ float sm[];
    float* bufA = sm;
    float* bufB = sm + WRR * WS;
    float* ring = sm + 2 * WRR * WS;
    __shared__ float s_r0[16], s_r1[16];

    const int tid = threadIdx.x;
    const int tx = tid & 31, ty = tid >> 5;
    const int tileIdx = blockIdx.x;
    const int img  = blockIdx.y;
    const int tY = (tileIdx >> 3) * TILE;
    const int tX = (tileIdx & 7)  * TILE;
    const int gy0 = tY - RAY, gx0 = tX - RAX;
    const bool edge = (tY == 0) || (tX == 0) || (tY == HW - TILE) || (tX == HW - TILE);
    const int vTop = (tY == 0)         ? 1 : 0;
    const int vBot = (tY == HW - TILE) ? 1 : 0;
    const int vL   = (tX == 0)         ? 1 : 0;
    const int vR   = (tX == HW - TILE) ? 1 : 0;

    const float* __restrict__ xin = x + (size_t)img * HW * HW;
    const int*   __restrict__ yin = y + (size_t)(img >> 1) * HW * HW;
    const int cls = img & 1;

    if (!vL && !vR) {
        for (int u = tid; u < WRR * 20; u += TPBA) {
            const int i = u / 20, cu = u - i * 20;
            *(float4*)(bufA + i * WS + cu * 4) =
                *(const float4*)(xin + iclamp(gy0 + i) * HW + gx0 + cu * 4);
        }
    } else {
        const int uLo = vL ? 2 : 0;
        for (int u = tid; u < WRR * 18; u += TPBA) {
            const int i = u / 18, cu = uLo + (u - i * 18);
            *(float4*)(bufA + i * WS + cu * 4) =
                *(const float4*)(xin + iclamp(gy0 + i) * HW + gx0 + cu * 4);
        }
    }

    int roff0, ci0, roff1 = -1, ci1 = 0;
    {
        int i, j;
        ring_cell(tid, i, j);
        roff0 = (RAY + i) * WS + (RAX + j);
        ci0   = (i + 2) * CLW + (j + 2);
        if (tid < NRING - TPBA) {
            ring_cell(tid + TPBA, i, j);
            roff1 = (RAY + i) * WS + (RAX + j);
            ci1   = (i + 2) * CLW + (j + 2);
        }
    }
    ring[tid] = 0.0f;
    if (tid < NRING - TPBA) ring[tid + TPBA] = 0.0f;

    __syncthreads();
    if (vL) for (int i = tid; i < WRR; i += TPBA) {
        const float v = bufA[i * WS + 8];
        #pragma unroll
        for (int j = 0; j < 8; j++) bufA[i * WS + j] = v;
    }
    if (vR) for (int i = tid; i < WRR; i += TPBA) {
        const float v = bufA[i * WS + RAX + TILE - 1];
        #pragma unroll
        for (int j = 0; j < 8; j++) bufA[i * WS + RAX + TILE + j] = v;
    }
    __syncthreads();

    float clr[2][4];
    #pragma unroll
    for (int c = 0; c < 2; c++)
        #pragma unroll
        for (int r = 0; r < 4; r++) clr[c][r] = 0.0f;

    float* pin  = bufA;
    float* pout = bufB;
    bool drained = false;

    for (int it = 0; it < KA; it++) {
        const int Hh = 6 - it;
        const int r0 = RAY - Hh, r1 = RAY + TILE + Hh;
        const int cLo = RAX - Hh, cHi = RAX + TILE + Hh;
        const int qlo = (cLo + 3) >> 2, qhi = (cHi - 4) >> 2;
        const int units = (r1 - r0) * 20;
        int nz = 0;
        for (int u = tid; u < units; u += TPBA) {
            const int rr = u / 20;
            const int c4 = u - rr * 20;
            const int base = (r0 + rr) * WS + c4 * 4;
            const float4 c = *(const float4*)(pin + base);
            if ((c.x == 0.0f) & (c.y == 0.0f) & (c.z == 0.0f) & (c.w == 0.0f)) {
                *(float4*)(pout + base) = make_float4(0.0f, 0.0f, 0.0f, 0.0f);
            } else {
                const float4 up = *(const float4*)(pin + base - WS);
                const float4 dn = *(const float4*)(pin + base + WS);
                const float lft = pin[base - 1];
                const float rgt = pin[base + 4];
                float4 o;
                o.x = fminf(fminf(fminf(lft, c.y), c.x), fminf(up.x, dn.x));
                o.y = fminf(fminf(fminf(c.x, c.z), c.y), fminf(up.y, dn.y));
                o.z = fminf(fminf(fminf(c.y, c.w), c.z), fminf(up.z, dn.z));
                o.w = fminf(fminf(fminf(c.z, rgt), c.w), fminf(up.w, dn.w));
                *(float4*)(pout + base) = o;
                if (c4 >= qlo && c4 <= qhi) {
                    nz |= (o.x != 0.0f) | (o.y != 0.0f) | (o.z != 0.0f) | (o.w != 0.0f);
                } else {
                    const int j0 = c4 * 4;
                    nz |= ((o.x != 0.0f) & (j0     >= cLo) & (j0     < cHi));
                    nz |= ((o.y != 0.0f) & (j0 + 1 >= cLo) & (j0 + 1 < cHi));
                    nz |= ((o.z != 0.0f) & (j0 + 2 >= cLo) & (j0 + 2 < cHi));
                    nz |= ((o.w != 0.0f) & (j0 + 3 >= cLo) & (j0 + 3 < cHi));
                }
            }
        }
        const int any = __syncthreads_or(nz);

        if (edge) {
            if (vTop) for (int i = r0 + ty; i < RAY; i += 16) {
                float* d = pout + i * WS; const float* s = pout + RAY * WS;
                for (int j = cLo + tx; j < cHi; j += 32) d[j] = s[j];
            }
            if (vBot) for (int i = RAY + TILE + ty; i < r1; i += 16) {
                float* d = pout + i * WS; const float* s = pout + (RAY + TILE - 1) * WS;
                for (int j = cLo + tx; j < cHi; j += 32) d[j] = s[j];
            }
            __syncthreads();
            if (vL) for (int i = r0 + ty; i < r1; i += 16) {
                const float s = pout[i * WS + RAX];
                for (int j = cLo + tx; j < RAX; j += 32) pout[i * WS + j] = s;
            }
            if (vR) for (int i = r0 + ty; i < r1; i += 16) {
                const float s = pout[i * WS + RAX + TILE - 1];
                for (int j = RAX + TILE + tx; j < cHi; j += 32) pout[i * WS + j] = s;
            }
            __syncthreads();
        }

        {
            const int rbase = RAY + ty * 4;
            float labv[2][4];
            int lz = 0;
            #pragma unroll
            for (int c = 0; c < 2; c++) {
                const float* lp = pin + rbase * WS + RAX + tx + c * 32;
                #pragma unroll
                for (int r = 0; r < 4; r++) {
                    labv[c][r] = lp[r * WS];
                    lz |= (labv[c][r] != 0.0f);
                }
            }
            if (__ballot_sync(0xffffffffu, lz)) {
                if (any) {
                    #pragma unroll
                    for (int c = 0; c < 2; c++) {
                        const int jj = RAX + tx + c * 32;
                        const float* p = pout + (rbase - 1) * WS + jj;
                        float h0 = fmaxf(fmaxf(p[-1], p[0]), p[1]); p += WS;
                        float h1 = fmaxf(fmaxf(p[-1], p[0]), p[1]); p += WS;
                        #pragma unroll
                        for (int r = 0; r < 4; r++) {
                            const float h2 = fmaxf(fmaxf(p[-1], p[0]), p[1]); p += WS;
                            const float m = fmaxf(fmaxf(h0, h1), h2);
                            const float t = labv[c][r] - m;
                            if (t > 0.0f) {
                                const float cv = clr[c][r];
                                clr[c][r] = cv + fmaxf((1.0f - cv) * t, 0.0f);
                            }
                            h0 = h1; h1 = h2;
                        }
                    }
                } else {
                    #pragma unroll
                    for (int c = 0; c < 2; c++)
                        #pragma unroll
                        for (int r = 0; r < 4; r++) {
                            const float t = labv[c][r];
                            if (t > 0.0f) {
                                const float cv = clr[c][r];
                                clr[c][r] = cv + fmaxf((1.0f - cv) * t, 0.0f);
                            }
                        }
                }
            }
        }

        {
            const float lab = pin[roff0];
            if (lab != 0.0f) {
                float m = 0.0f;
                if (any) {
                    const float* p = pout + roff0;
                    m =          fmaxf(fmaxf(p[-1 - WS], p[-WS]), p[1 - WS]);
                    m = fmaxf(m, fmaxf(fmaxf(p[-1],      p[0]),  p[1]));
                    m = fmaxf(m, fmaxf(fmaxf(p[-1 + WS], p[WS]), p[1 + WS]));
                }
                const float t = lab - m;
                if (t > 0.0f) {
                    const float cv = ring[tid];
                    ring[tid] = cv + fmaxf((1.0f - cv) * t, 0.0f);
                }
            }
            if (roff1 >= 0) {
                const float lab2 = pin[roff1];
                if (lab2 != 0.0f) {
                    float m = 0.0f;
                    if (any) {
                        const float* p = pout + roff1;
                        m =          fmaxf(fmaxf(p[-1 - WS], p[-WS]), p[1 - WS]);
                        m = fmaxf(m, fmaxf(fmaxf(p[-1],      p[0]),  p[1]));
                        m = fmaxf(m, fmaxf(fmaxf(p[-1 + WS], p[WS]), p[1 + WS]));
                    }
                    const float t = lab2 - m;
                    if (t > 0.0f) {
                        const float cv = ring[tid + TPBA];
                        ring[tid + TPBA] = cv + fmaxf((1.0f - cv) * t, 0.0f);
                    }
                }
            }
        }
        __syncthreads();
        float* tmp = pin; pin = pout; pout = tmp;
        if (!any) { drained = true; break; }
    }

    int tnz = 0;
    if (!drained) {
        int hz = 0;
        for (int u = tid; u < 68 * 18; u += TPBA) {
            const int r = u / 18, cu = u - r * 18;
            const float4 c = *(const float4*)(pin + (5 + r) * WS + 4 + cu * 4);
            const int nzv = (c.x != 0.0f) | (c.y != 0.0f) | (c.z != 0.0f) | (c.w != 0.0f);
            hz |= nzv;
            tnz |= nzv & (r >= 2) & (r < 66);
        }
        hz  = __syncthreads_or(hz);
        tnz = __syncthreads_or(tnz);
        drained = !hz;
    }

    float* __restrict__ gc = &g_cl[0][img][0][0];
    #pragma unroll
    for (int r = 0; r < 4; r++) {
        const int row = ty * 4 + r;
        float* go = gc + (tY + row) * HW + tX;
        go[tx]      = clr[0][r];
        go[tx + 32] = clr[1][r];
    }
    if (tnz) {
        float* __restrict__ gl = &g_lab[0][img][0][0];
        #pragma unroll
        for (int r = 0; r < 4; r++) {
            const int row = ty * 4 + r;
            const float* lr = pin + (RAY + row) * WS + RAX;
            float* go = gl + (tY + row) * HW + tX;
            go[tx]      = lr[tx];
            go[tx + 32] = lr[tx + 32];
        }
    }
    if (tid == 0) g_flag[0][img][tileIdx] = tnz;

    if (!drained) return;

    float* CLS = pout;
    #pragma unroll
    for (int r = 0; r < 4; r++) {
        const int row = ty * 4 + r;
        float* cr = CLS + (2 + row) * CLW + 2;
        cr[tx]      = clr[0][r];
        cr[tx + 32] = clr[1][r];
    }
    CLS[ci0] = ring[tid];
    if (roff1 >= 0) CLS[ci1] = ring[tid + TPBA];
    __syncthreads();

    if (edge) {
        if (vTop)
            for (int k = tid; k < 2 * CLW; k += TPBA) CLS[(k / CLW) * CLW + k % CLW] = CLS[2 * CLW + k % CLW];
        if (vBot)
            for (int k = tid; k < 2 * CLW; k += TPBA) CLS[(66 + k / CLW) * CLW + k % CLW] = CLS[65 * CLW + k % CLW];
        __syncthreads();
        if (vL)
            for (int k = tid; k < 2 * CLW; k += TPBA) CLS[(k >> 1) * CLW + (k & 1)] = CLS[(k >> 1) * CLW + 2];
        if (vR)
            for (int k = tid; k < 2 * CLW; k += TPBA) CLS[(k >> 1) * CLW + 66 + (k & 1)] = CLS[(k >> 1) * CLW + 65];
        __syncthreads();
    }

    float* HB = pin;
    for (int u = tid; u < 68 * 17; u += TPBA) {
        const int r = u / 17, cu = u - r * 17;
        const int b = r * CLW + cu * 4;
        const float4 A = *(const float4*)(CLS + b);
        const float4 B = *(const float4*)(CLS + b + 4);
        float4 o;
        o.x = fmaxf(fmaxf(A.x, A.y), A.z);
        o.y = fmaxf(fmaxf(A.y, A.z), A.w);
        o.z = fmaxf(fmaxf(A.z, A.w), B.x);
        o.w = fmaxf(fmaxf(A.w, B.x), B.y);
        *(float4*)(HB + b) = o;
    }
    __syncthreads();
    float* D = CLS;
    for (int u = tid; u < 66 * 17; u += TPBA) {
        const int d = u / 17, cu = u - d * 17;
        const int b = d * CLW + cu * 4;
        const float4 A  = *(const float4*)(HB + b);
        const float4 Bv = *(const float4*)(HB + b + CLW);
        const float4 Cv = *(const float4*)(HB + b + 2 * CLW);
        float4 o;
        o.x = fmaxf(fmaxf(A.x, Bv.x), Cv.x);
        o.y = fmaxf(fmaxf(A.y, Bv.y), Cv.y);
        o.z = fmaxf(fmaxf(A.z, Bv.z), Cv.z);
        o.w = fmaxf(fmaxf(A.w, Bv.w), Cv.w);
        *(float4*)(D + b) = o;
    }
    __syncthreads();
    if (edge) {
        if (vTop) for (int e = tid; e < DW; e += TPBA) D[e]              = D[CLW + e];
        if (vBot) for (int e = tid; e < DW; e += TPBA) D[65 * CLW + e]   = D[64 * CLW + e];
        __syncthreads();
        if (vL)   for (int d = tid; d < DW; d += TPBA) D[d * CLW]        = D[d * CLW + 1];
        if (vR)   for (int d = tid; d < DW; d += TPBA) D[d * CLW + 65]   = D[d * CLW + 64];
        __syncthreads();
    }

    float s0 = 0.0f, s1 = 0.0f;
    for (int u = tid; u < 1024; u += TPBA) {
        const int i2 = u >> 4, cu = u & 15;
        const int c0 = cu * 4;
        const float* rc = D + (i2 + 1) * CLW + c0;
        const float4 A = *(const float4*)(rc);
        const float b0 = rc[4], b1 = rc[5];
        float v0 = fminf(A.y, fminf(A.x, A.z));
        float v1 = fminf(A.z, fminf(A.y, A.w));
        float v2 = fminf(A.w, fminf(A.z, b0));
        float v3 = fminf(b0,  fminf(A.w, b1));
        {
            const float4 Au = *(const float4*)(rc - CLW);
            v0 = fminf(v0, Au.y); v1 = fminf(v1, Au.z); v2 = fminf(v2, Au.w);
            v3 = fminf(v3, rc[-CLW + 4]);
        }
        {
            const float4 Ad = *(const float4*)(rc + CLW);
            v0 = fminf(v0, Ad.y); v1 = fminf(v1, Ad.z); v2 = fminf(v2, Ad.w);
            v3 = fminf(v3, rc[CLW + 4]);
        }
        const int gy = tY + i2, gxb = tX + c0;
        const int4 yy = *(const int4*)(yin + gy * HW + gxb);
        const float w0 = (yy.x == cls) ? 1.0f : 0.0f;
        const float w1 = (yy.y == cls) ? 1.0f : 0.0f;
        const float w2 = (yy.z == cls) ? 1.0f : 0.0f;
        const float w3 = (yy.w == cls) ? 1.0f : 0.0f;
        s0 += v0 * w0 + v1 * w1 + v2 * w2 + v3 * w3;
        s1 += (v0 + v1) + (v2 + v3);
    }
    for (int o = 16; o > 0; o >>= 1) {
        s0 += __shfl_down_sync(0xffffffffu, s0, o);
        s1 += __shfl_down_sync(0xffffffffu, s1, o);
    }
    if (tx == 0) { s_r0[ty] = s0; s_r1[ty] = s1; }
    __syncthreads();
    if (tid < 16) {
        s0 = s_r0[tid]; s1 = s_r1[tid];
        for (int o = 8; o > 0; o >>= 1) {
            s0 += __shfl_down_sync(0xffffu, s0, o);
            s1 += __shfl_down_sync(0xffffu, s1, o);
        }
        if (tid == 0) {
            g_part[0][img][tileIdx][0] = s0;
            g_part[0][img][tileIdx][1] = s1;
        }
    }
}

// ---------------------------------------------------------------------------
// phaseL: label pipe (pipe 1), bitwise. Row = 3 uint32 words (cols 0..79),
// stride 4. All ops on {0,1} are exact; cl |= lab & ~dilate3x3(nl).
// ---------------------------------------------------------------------------
__global__ void __launch_bounds__(TPBA) phaseL_kernel(const float* __restrict__ x,
                                                      const int*   __restrict__ y) {
    __shared__ unsigned BA[WRR * 4], BB[WRR * 4], CLB[WRR * 4];
    __shared__ unsigned HBb[WRR * 4], DBb[WRR * 4], VBb[64 * 4];
    __shared__ float s_r0[16], s_r1[16];

    const int tid = threadIdx.x;
    const int tx = tid & 31, wy = tid >> 5;
    const int tileIdx = blockIdx.x;
    const int img = blockIdx.y;
    const int tY = (tileIdx >> 3) * TILE;
    const int tX = (tileIdx & 7)  * TILE;
    const bool edge = (tY == 0) || (tX == 0) || (tY == HW - TILE) || (tX == HW - TILE);
    const int vTop = (tY == 0)         ? 1 : 0;
    const int vBot = (tY == HW - TILE) ? 1 : 0;
    const int vL   = (tX == 0)         ? 1 : 0;
    const int vR   = (tX == HW - TILE) ? 1 : 0;

    const float* __restrict__ xin = x + (size_t)img * HW * HW;
    const int*   __restrict__ yin = y + (size_t)(img >> 1) * HW * HW;
    const int cls = img & 1;

    // Ballot-pack the one-hot map (clamped indexing = replicate pad).
    for (int s = wy; s < WRR * 3; s += 16) {
        const int row = s / 3, w = s - row * 3;
        const int gy = iclamp(tY - RAY + row);
        const int gx = iclamp(tX - RAX + w * 32 + tx);
        const unsigned bits = __ballot_sync(0xffffffffu, yin[gy * HW + gx] == cls);
        if (tx == 0) BA[row * 4 + w] = (w == 2) ? (bits & 0xFFFFu) : bits;
    }
    if (tid < WRR) { BA[tid * 4 + 3] = 0u; BB[tid * 4 + 3] = 0u; }
    for (int k = tid; k < WRR * 4; k += TPBA) CLB[k] = 0u;
    __syncthreads();

    const unsigned clm0 = 0xFFFFFFC0u, clm2 = 0x3FFu;   // cl band cols [6,74)
    unsigned* pin  = BA;
    unsigned* pout = BB;
    bool drained = false;

    for (int it = 0; it < KA; it++) {
        const int Hh = 6 - it;
        const int r0 = RAY - Hh, r1 = RAY + TILE + Hh;
        const int cLo = RAX - Hh, cHi = RAX + TILE + Hh;
        unsigned m[3];
        #pragma unroll
        for (int w = 0; w < 3; w++) {
            int lo = cLo - 32 * w; if (lo < 0) lo = 0;
            int hi = cHi - 32 * w; if (hi > 32) hi = 32;
            m[w] = (hi <= lo) ? 0u
                 : (((hi == 32) ? 0xFFFFFFFFu : ((1u << hi) - 1u)) & ~((1u << lo) - 1u));
        }
        unsigned nz = 0u;
        for (int i = r0 + tid; i < r1; i += TPBA) {
            const unsigned c0 = pin[i*4], c1 = pin[i*4+1], c2 = pin[i*4+2];
            const unsigned u0 = pin[(i-1)*4], u1 = pin[(i-1)*4+1], u2 = pin[(i-1)*4+2];
            const unsigned d0 = pin[(i+1)*4], d1 = pin[(i+1)*4+1], d2 = pin[(i+1)*4+2];
            const unsigned o0 = c0 & (c0 << 1) & ((c0 >> 1) | (c1 << 31)) & u0 & d0;
            const unsigned o1 = c1 & ((c1 << 1) | (c0 >> 31)) & ((c1 >> 1) | (c2 << 31)) & u1 & d1;
            const unsigned o2 = c2 & ((c2 << 1) | (c1 >> 31)) & (c2 >> 1) & u2 & d2;
            pout[i*4] = o0; pout[i*4+1] = o1; pout[i*4+2] = o2;
            nz |= (o0 & m[0]) | (o1 & m[1]) | (o2 & m[2]);
        }
        const int any = __syncthreads_or(nz != 0u);

        if (edge) {
            if (vTop) for (int i = r0 + tid; i < RAY; i += TPBA) {
                pout[i*4] = pout[RAY*4]; pout[i*4+1] = pout[RAY*4+1]; pout[i*4+2] = pout[RAY*4+2];
            }
            if (vBot) for (int i = RAY + TILE + tid; i < r1; i += TPBA) {
                pout[i*4] = pout[(RAY+TILE-1)*4]; pout[i*4+1] = pout[(RAY+TILE-1)*4+1];
                pout[i*4+2] = pout[(RAY+TILE-1)*4+2];
            }
            __syncthreads();
            if (vL) for (int i = r0 + tid; i < r1; i += TPBA) {
                const unsigned w0 = pout[i*4];
                pout[i*4] = (w0 & ~0xFFu) | (((w0 >> 8) & 1u) ? 0xFFu : 0u);
            }
            if (vR) for (int i = r0 + tid; i < r1; i += TPBA) {
                const unsigned w2 = pout[i*4+2];
                pout[i*4+2] = (w2 & 0xFFu) | (((w2 >> 7) & 1u) ? 0xFF00u : 0u);
            }
            __syncthreads();
        }

        // cl |= lab & ~dilate3x3(nl), rows 5..72, cols [6,74)
        for (int i = 5 + tid; i < 73; i += TPBA) {
            unsigned dd0 = 0u, dd1 = 0u, dd2 = 0u;
            if (any) {
                #pragma unroll
                for (int dr = -1; dr <= 1; dr++) {
                    const unsigned n0 = pout[(i+dr)*4], n1 = pout[(i+dr)*4+1], n2 = pout[(i+dr)*4+2];
                    dd0 |= n0 | (n0 << 1) | ((n0 >> 1) | (n1 << 31));
                    dd1 |= n1 | ((n1 << 1) | (n0 >> 31)) | ((n1 >> 1) | (n2 << 31));
                    dd2 |= n2 | ((n2 << 1) | (n1 >> 31)) | (n2 >> 1);
                }
            }
            CLB[i*4]   |= pin[i*4]   & ~dd0 & clm0;
            CLB[i*4+1] |= pin[i*4+1] & ~dd1;
            CLB[i*4+2] |= pin[i*4+2] & ~dd2 & clm2;
        }
        __syncthreads();
        unsigned* tmp = pin; pin = pout; pout = tmp;
        if (!any) { drained = true; break; }
    }

    int tnz = 0;
    if (!drained) {
        unsigned hz = 0u, tz = 0u;
        for (int i = 5 + tid; i < 73; i += TPBA) {
            hz |= (pin[i*4] & clm0) | pin[i*4+1] | (pin[i*4+2] & clm2);
            if (i >= 7 && i < 71)
                tz |= (pin[i*4] & 0xFFFFFF00u) | pin[i*4+1] | (pin[i*4+2] & 0xFFu);
        }
        const int hza = __syncthreads_or(hz != 0u);
        tnz = __syncthreads_or(tz != 0u);
        drained = !hza;
    }

    // Publish cl float; lab_4 float if tile nonzero; flag.
    const int prow = tid >> 3, pseg = tid & 7;     // 64 rows x 8 segs
    const int col0 = RAX + pseg * 8;
    const int pw = col0 >> 5, pb = col0 & 31;
    {
        float* gp = &g_cl[1][img][0][0] + (tY + prow) * HW + tX + pseg * 8;
        const unsigned bits = CLB[(RAY + prow) * 4 + pw] >> pb;
        float4 fa, fb;
        fa.x = (float)((bits >> 0) & 1u); fa.y = (float)((bits >> 1) & 1u);
        fa.z = (float)((bits >> 2) & 1u); fa.w = (float)((bits >> 3) & 1u);
        fb.x = (float)((bits >> 4) & 1u); fb.y = (float)((bits >> 5) & 1u);
        fb.z = (float)((bits >> 6) & 1u); fb.w = (float)((bits >> 7) & 1u);
        *(float4*)(gp)     = fa;
        *(float4*)(gp + 4) = fb;
    }
    if (tnz) {
        float* gp = &g_lab[1][img][0][0] + (tY + prow) * HW + tX + pseg * 8;
        const unsigned bits = pin[(RAY + prow) * 4 + pw] >> pb;
        float4 fa, fb;
        fa.x = (float)((bits >> 0) & 1u); fa.y = (float)((bits >> 1) & 1u);
        fa.z = (float)((bits >> 2) & 1u); fa.w = (float)((bits >> 3) & 1u);
        fb.x = (float)((bits >> 4) & 1u); fb.y = (float)((bits >> 5) & 1u);
        fb.z = (float)((bits >> 6) & 1u); fb.w = (float)((bits >> 7) & 1u);
        *(float4*)(gp)     = fa;
        *(float4*)(gp + 4) = fb;
    }
    if (tid == 0) g_flag[1][img][tileIdx] = tnz;

    if (!drained) return;   // slowB owns this tile's partials

    // ---------- drained: bitwise pools + fused reduction ----------
    if (edge) {
        if (vTop) for (int i = 5 + tid; i < 7; i += TPBA) {
            CLB[i*4] = CLB[7*4]; CLB[i*4+1] = CLB[7*4+1]; CLB[i*4+2] = CLB[7*4+2];
        }
        if (vBot) for (int i = 71 + tid; i < 73; i += TPBA) {
            CLB[i*4] = CLB[70*4]; CLB[i*4+1] = CLB[70*4+1]; CLB[i*4+2] = CLB[70*4+2];
        }
        __syncthreads();
        if (vL) for (int i = 5 + tid; i < 73; i += TPBA) {
            const unsigned w0 = CLB[i*4];
            CLB[i*4] = (w0 & ~0xC0u) | (((w0 >> 8) & 1u) ? 0xC0u : 0u);
        }
        if (vR) for (int i = 5 + tid; i < 73; i += TPBA) {
            const unsigned w2 = CLB[i*4+2];
            CLB[i*4+2] = (w2 & ~0x300u) | (((w2 >> 7) & 1u) ? 0x300u : 0u);
        }
        __syncthreads();
    }

    // H = horizontal dilation, rows 5..72
    for (int i = 5 + tid; i < 73; i += TPBA) {
        const unsigned c0 = CLB[i*4], c1 = CLB[i*4+1], c2 = CLB[i*4+2];
        HBb[i*4]   = c0 | (c0 << 1) | ((c0 >> 1) | (c1 << 31));
        HBb[i*4+1] = c1 | ((c1 << 1) | (c0 >> 31)) | ((c1 >> 1) | (c2 << 31));
        HBb[i*4+2] = c2 | ((c2 << 1) | (c1 >> 31)) | (c2 >> 1);
    }
    __syncthreads();
    // D = vertical dilation, rows 6..71
    for (int i = 6 + tid; i < 72; i += TPBA) {
        DBb[i*4]   = HBb[(i-1)*4]   | HBb[i*4]   | HBb[(i+1)*4];
        DBb[i*4+1] = HBb[(i-1)*4+1] | HBb[i*4+1] | HBb[(i+1)*4+1];
        DBb[i*4+2] = HBb[(i-1)*4+2] | HBb[i*4+2] | HBb[(i+1)*4+2];
    }
    __syncthreads();
    if (edge) {
        if (vTop && tid == 0) { DBb[6*4] = DBb[7*4]; DBb[6*4+1] = DBb[7*4+1]; DBb[6*4+2] = DBb[7*4+2]; }
        if (vBot && tid == 0) { DBb[71*4] = DBb[70*4]; DBb[71*4+1] = DBb[70*4+1]; DBb[71*4+2] = DBb[70*4+2]; }
        __syncthreads();
        if (vL) for (int i = 6 + tid; i < 72; i += TPBA) {
            const unsigned w0 = DBb[i*4];
            DBb[i*4] = (w0 & ~0x80u) | (((w0 >> 8) & 1u) ? 0x80u : 0u);
        }
        if (vR) for (int i = 6 + tid; i < 72; i += TPBA) {
            const unsigned w2 = DBb[i*4+2];
            DBb[i*4+2] = (w2 & ~0x100u) | (((w2 >> 7) & 1u) ? 0x100u : 0u);
        }
        __syncthreads();
    }
    // v = plus-shaped AND-erosion of D, tile rows 7..70, cols [8,72)
    for (int i = 7 + tid; i < 71; i += TPBA) {
        const unsigned c0 = DBb[i*4], c1 = DBb[i*4+1], c2 = DBb[i*4+2];
        const unsigned u0 = DBb[(i-1)*4], u1 = DBb[(i-1)*4+1], u2 = DBb[(i-1)*4+2];
        const unsigned d0 = DBb[(i+1)*4], d1 = DBb[(i+1)*4+1], d2 = DBb[(i+1)*4+2];
        const unsigned v0 = c0 & (c0 << 1) & ((c0 >> 1) | (c1 << 31)) & u0 & d0;
        const unsigned v1 = c1 & ((c1 << 1) | (c0 >> 31)) & ((c1 >> 1) | (c2 << 31)) & u1 & d1;
        const unsigned v2 = c2 & ((c2 << 1) | (c1 >> 31)) & (c2 >> 1) & u2 & d2;
        VBb[(i-7)*4]   = v0 & 0xFFFFFF00u;
        VBb[(i-7)*4+1] = v1;
        VBb[(i-7)*4+2] = v2 & 0xFFu;
    }
    __syncthreads();

    float s0 = 0.0f, s1 = 0.0f;
    {
        const unsigned bits = (VBb[prow * 4 + pw] >> pb) & 0xFFu;
        const float* xr = xin + (tY + prow) * HW + tX + pseg * 8;
        const float4 xa = *(const float4*)(xr);
        const float4 xb = *(const float4*)(xr + 4);
        if (bits & 0x01u) s0 += xa.x;
        if (bits & 0x02u) s0 += xa.y;
        if (bits & 0x04u) s0 += xa.z;
        if (bits & 0x08u) s0 += xa.w;
        if (bits & 0x10u) s0 += xb.x;
        if (bits & 0x20u) s0 += xb.y;
        if (bits & 0x40u) s0 += xb.z;
        if (bits & 0x80u) s0 += xb.w;
        s1 = (float)__popc(bits);
    }
    for (int o = 16; o > 0; o >>= 1) {
        s0 += __shfl_down_sync(0xffffffffu, s0, o);
        s1 += __shfl_down_sync(0xffffffffu, s1, o);
    }
    if (tx == 0) { s_r0[wy] = s0; s_r1[wy] = s1; }
    __syncthreads();
    if (tid < 16) {
        s0 = s_r0[tid]; s1 = s_r1[tid];
        for (int o = 8; o > 0; o >>= 1) {
            s0 += __shfl_down_sync(0xffffu, s0, o);
            s1 += __shfl_down_sync(0xffffu, s1, o);
        }
        if (tid == 0) {
            g_part[1][img][tileIdx][0] = s0;
            g_part[1][img][tileIdx][1] = s1;
        }
    }
}

// ---------------------------------------------------------------------------
// slowB: tiles with any 3x3 covering flag set: iterations 4..20 + pools +
// reduction. Exits immediately otherwise.
// ---------------------------------------------------------------------------
__global__ void __launch_bounds__(TPB) slowB_kernel(const float* __restrict__ x,
                                                    const int*   __restrict__ y) {
    extern __shared__ float sm[];
    float* bufA = sm;
    float* bufB = sm + WB * WB;
    float* CLBf = sm + 2 * WB * WB;
    __shared__ float s_r0[8], s_r1[8];
    __shared__ int s_flags[9];

    const int tid = threadIdx.x;
    const int tx = tid & 31, ty = tid >> 5;
    const int tileIdx = blockIdx.x;
    const int img  = blockIdx.y;
    const int pipe = blockIdx.z;
    const int tr = tileIdx >> 3, tc = tileIdx & 7;
    const int tY = tr * TILE, tX = tc * TILE;
    const int gy0 = tY - RB, gx0 = tX - RB;
    const bool edge = (tY == 0) || (tX == 0) || (tY == HW - TILE) || (tX == HW - TILE);

    if (tid < 9) {
        const int rr = tr + tid / 3 - 1, cc = tc + tid % 3 - 1;
        int f = 0;
        if (rr >= 0 && rr < 8 && cc >= 0 && cc < 8) f = g_flag[pipe][img][rr * 8 + cc];
        s_flags[tid] = f;
    }
    __syncthreads();
    int anyLab = 0;
    #pragma unroll
    for (int k = 0; k < 9; k++) anyLab |= s_flags[k];
    if (!anyLab) return;

    const float* __restrict__ gl = &g_lab[pipe][img][0][0];
    const float* __restrict__ gc = &g_cl [pipe][img][0][0];

    for (int i = ty; i < CLW; i += 8) {
        const int gy = iclamp(tY - 2 + i);
        float* d = CLBf + i * CLW;
        for (int j = tx; j < CLW; j += 32) d[j] = gc[gy * HW + iclamp(tX - 2 + j)];
    }
    for (int i = ty; i < WB; i += 8) {
        const int gy = iclamp(gy0 + i);
        const int fr = (gy >> 6) - (tr - 1);
        for (int j = tx; j < WB; j += 32) {
            const int gx = iclamp(gx0 + j);
            const int fc = (gx >> 6) - (tc - 1);
            bufA[i * WB + j] = s_flags[fr * 3 + fc] ? gl[gy * HW + gx] : 0.0f;
        }
    }
    __syncthreads();

    float* pin  = bufA;
    float* pout = bufB;
    for (int it = 0; it < KB; it++) {
        int Hh = 19 - it; if (Hh < 3) Hh = 3;
        const int r0 = RB - Hh, r1 = RB + TILE + Hh;
        int nz = 0;
        for (int i = r0 + ty; i < r1; i += 8) {
            const int gy = gy0 + i;
            if (gy < 0 || gy >= HW) continue;
            const int iu = (gy > 0)      ? i - 1 : i;
            const int id = (gy < HW - 1) ? i + 1 : i;
            for (int j = r0 + tx; j < r1; j += 32) {
                const int gx = gx0 + j;
                if (gx < 0 || gx >= HW) continue;
                const int jl = (gx > 0)      ? j - 1 : j;
                const int jr = (gx < HW - 1) ? j + 1 : j;
                float v = pin[i * WB + j];
                v = fminf(v, pin[iu * WB + j]);
                v = fminf(v, pin[id * WB + j]);
                v = fminf(v, pin[i * WB + jl]);
                v = fminf(v, pin[i * WB + jr]);
                pout[i * WB + j] = v;
                nz |= (v != 0.0f);
            }
        }
        const int any = __syncthreads_or(nz);
        for (int i = RB - 2 + ty; i < RB + TILE + 2; i += 8) {
            const int gy = gy0 + i;
            if (gy < 0 || gy >= HW) continue;
            const int iu = (gy > 0)      ? i - 1 : i;
            const int id = (gy < HW - 1) ? i + 1 : i;
            for (int j = RB - 2 + tx; j < RB + TILE + 2; j += 32) {
                const int gx = gx0 + j;
                if (gx < 0 || gx >= HW) continue;
                const int jl = (gx > 0)      ? j - 1 : j;
                const int jr = (gx < HW - 1) ? j + 1 : j;
                float m;
                m =          pout[iu * WB + jl];
                m = fmaxf(m, pout[iu * WB + j ]);
                m = fmaxf(m, pout[iu * WB + jr]);
                m = fmaxf(m, pout[i  * WB + jl]);
                m = fmaxf(m, pout[i  * WB + j ]);
                m = fmaxf(m, pout[i  * WB + jr]);
                m = fmaxf(m, pout[id * WB + jl]);
                m = fmaxf(m, pout[id * WB + j ]);
                m = fmaxf(m, pout[id * WB + jr]);
                const float lab = pin[i * WB + j];
                const int ci = (i - (RB - 2)) * CLW + (j - (RB - 2));
                const float cl = CLBf[ci];
                const float t = fmaxf(lab - m, 0.0f);
                CLBf[ci] = cl + fmaxf((1.0f - cl) * t, 0.0f);
            }
        }
        __syncthreads();
        float* tmp = pin; pin = pout; pout = tmp;
        if (!any) break;
    }

    if (edge) {
        if (tY == 0)
            for (int k = tid; k < 2 * CLW; k += TPB) CLBf[(k / CLW) * CLW + k % CLW] = CLBf[2 * CLW + k % CLW];
        if (tY == HW - TILE)
            for (int k = tid; k < 2 * CLW; k += TPB) CLBf[(66 + k / CLW) * CLW + k % CLW] = CLBf[65 * CLW + k % CLW];
        __syncthreads();
        if (tX == 0)
            for (int k = tid; k < 2 * CLW; k += TPB) CLBf[(k >> 1) * CLW + (k & 1)] = CLBf[(k >> 1) * CLW + 2];
        if (tX == HW - TILE)
            for (int k = tid; k < 2 * CLW; k += TPB) CLBf[(k >> 1) * CLW + 66 + (k & 1)] = CLBf[(k >> 1) * CLW + 65];
        __syncthreads();
    }

    float* Hb = bufB;
    for (int c = ty; c < CLW; c += 8) {
        const float* r = CLBf + c * CLW;
        float* hb = Hb + c * DW;
        for (int e = tx; e < DW; e += 32)
            hb[e] = fmaxf(fmaxf(r[e], r[e + 1]), r[e + 2]);
    }
    __syncthreads();
    float* D = bufA;
    for (int d = ty; d < DW; d += 8) {
        const float* h = Hb + d * DW;
        float* dd = D + d * DW;
        for (int e = tx; e < DW; e += 32)
            dd[e] = fmaxf(fmaxf(h[e], h[e + DW]), h[e + 2 * DW]);
    }
    __syncthreads();
    if (edge) {
        if (tY == 0)          for (int e = tid; e < DW; e += TPB) D[e]           = D[DW + e];
        if (tY == HW - TILE)  for (int e = tid; e < DW; e += TPB) D[65 * DW + e] = D[64 * DW + e];
        __syncthreads();
        if (tX == 0)          for (int d = tid; d < DW; d += TPB) D[d * DW]      = D[d * DW + 1];
        if (tX == HW - TILE)  for (int d = tid; d < DW; d += TPB) D[d * DW + 65] = D[d * DW + 64];
        __syncthreads();
    }

    const float* __restrict__ xin = x + (size_t)img * HW * HW;
    const int*   __restrict__ yin = y + (size_t)(img >> 1) * HW * HW;
    const int cls = img & 1;
    float s0 = 0.0f, s1 = 0.0f;
    for (int i2 = ty; i2 < TILE; i2 += 8) {
        const int gy = tY + i2;
        const float* dc = D + (i2 + 1) * DW;
        for (int j2 = tx; j2 < TILE; j2 += 32) {
            const int e = j2 + 1;
            float v = fminf(fminf(dc[e - 1], dc[e]), dc[e + 1]);
            v = fminf(v, fminf(dc[e - DW], dc[e + DW]));
            const float w = (pipe == 0) ? ((yin[gy * HW + tX + j2] == cls) ? 1.0f : 0.0f)
                                        : xin[gy * HW + tX + j2];
            s0 += v * w;
            s1 += v;
        }
    }
    for (int o = 16; o > 0; o >>= 1) {
        s0 += __shfl_down_sync(0xffffffffu, s0, o);
        s1 += __shfl_down_sync(0xffffffffu, s1, o);
    }
    if (tx == 0) { s_r0[ty] = s0; s_r1[ty] = s1; }
    __syncthreads();
    if (tid < 8) {
        s0 = s_r0[tid]; s1 = s_r1[tid];
        for (int o = 4; o > 0; o >>= 1) {
            s0 += __shfl_down_sync(0xffu, s0, o);
            s1 += __shfl_down_sync(0xffu, s1, o);
        }
        if (tid == 0) {
            g_part[pipe][img][tileIdx][0] = s0;
            g_part[pipe][img][tileIdx][1] = s1;
        }
    }
}

// ---------------------------------------------------------------------------
__global__ void __launch_bounds__(TPBA) finalize_kernel(float* __restrict__ out) {
    __shared__ float sdc[16];
    const int w = threadIdx.x >> 5;
    const int l = threadIdx.x & 31;
    float np = 0.0f, dp = 0.0f, nl2 = 0.0f, dl = 0.0f;
    #pragma unroll
    for (int k = l; k < 64; k += 32) {
        np  += g_part[0][w][k][0];
        dp  += g_part[0][w][k][1];
        nl2 += g_part[1][w][k][0];
        dl  += g_part[1][w][k][1];
    }
    for (int o = 16; o > 0; o >>= 1) {
        np  += __shfl_down_sync(0xffffffffu, np,  o);
        dp  += __shfl_down_sync(0xffffffffu, dp,  o);
        nl2 += __shfl_down_sync(0xffffffffu, nl2, o);
        dl  += __shfl_down_sync(0xffffffffu, dl,  o);
    }
    if (l == 0) {
        const float a = (np  + EPSF) / (dp + EPSF);
        const float b = (nl2 + EPSF) / (dl + EPSF);
        sdc[w] = 2.0f * a * b / (a + b);
    }
    __syncthreads();
    if (threadIdx.x < 32) {
        float dc = (threadIdx.x < 16) ? sdc[threadIdx.x] : 0.0f;
        for (int o = 16; o > 0; o >>= 1) dc += __shfl_down_sync(0xffffffffu, dc, o);
        if (threadIdx.x == 0) out[0] = -(dc * (1.0f / 16.0f));
    }
}

// ---------------------------------------------------------------------------
extern "C" void kernel_launch(void* const* d_in, const int* in_sizes, int n_in,
                              void* d_out, int out_size) {
    const float* x = (const float*)d_in[0];
    const int*   y = (const int*)d_in[1];
    float* out = (float*)d_out;

    const int smA = (2 * WRR * WS + NRING + 16) * (int)sizeof(float);   // 52,096 B
    const int smB = (2 * WB * WB + CLW * CLW) * (int)sizeof(float);     // 105,024 B
    cudaFuncSetAttribute(phaseA_kernel, cudaFuncAttributeMaxDynamicSharedMemorySize, smA);
    cudaFuncSetAttribute(slowB_kernel,  cudaFuncAttributeMaxDynamicSharedMemorySize, smB);

    phaseA_kernel<<<dim3(64, NIMG, 1), TPBA, smA>>>(x, y);
    phaseL_kernel<<<dim3(64, NIMG, 1), TPBA>>>(x, y);
    slowB_kernel<<<dim3(64, NIMG, 2), TPB, smB>>>(x, y);
    finalize_kernel<<<1, TPBA>>>(out);
    (void)in_sizes; (void)n_in; (void)out_size;
}